// round 6
// baseline (speedup 1.0000x reference)
#include <cuda_runtime.h>
#include <math.h>

#define S    48
#define MD   10
#define H    48
#define NF   60
#define CH   16            // rows per chunk (3 chunks of 16 = 48 rows)
#define CST  161           // chunk stride in floats per traj (160 + 1 pad; 161%32=1 -> conflict-free)
#define FST  61            // feature row stride (61%32=29, odd -> conflict-free)
#define MAXB 65536
#define WST  68            // kernel B: transposed-W row stride

__device__ float g_feat[(size_t)MAXB * NF];   // intermediate features

__device__ __forceinline__ float fsqrt_fast(float x){ return x * rsqrtf(x); }
__device__ __forceinline__ float wsum(float v){
  #pragma unroll
  for(int o=16;o;o>>=1) v += __shfl_xor_sync(0xffffffffu,v,o);
  return v;
}

// ================= Kernel A: features, one trajectory per LANE =================
__global__ __launch_bounds__(32)
void featA(const float* __restrict__ coords, const int* __restrict__ lengths, int B)
{
  __shared__ float shC[32*CST];     // 32 traj x 160-float chunk (padded)
  __shared__ float shFeat[32*FST];  // 32 traj x 60 features (padded)

  int t = threadIdx.x;              // lane = local trajectory
  int base = blockIdx.x * 32;
  int b = base + t;
  bool act = (b < B);
  int n = act ? lengths[b] : 4;
  int m = n - 1;
  int half = m >> 1;
  int tmax = B - base; if (tmax > 32) tmax = 32;

  // per-lane accumulators (registers only — no reductions anywhere)
  float cur[MD], pd[MD], su[MD], dv[MD];
  float pinv = 0.f;
  float sc=0.f, scq=0.f;
  float s_dm=0.f, s_dmsq=0.f, s_f=0.f, s_s=0.f, s_usq=0.f;
  float s_curv=0.f, s_curvsq=0.f, s_cos=0.f, s_neg=0.f;
  float mx_dm=-INFINITY, mx_curv=-INFINITY, nmn_curv=-INFINITY, nmn_cos=-INFINITY;
  #pragma unroll
  for (int j=0;j<MD;j++){ su[j]=0.f; dv[j]=0.f; pd[j]=0.f; cur[j]=0.f; }

  for (int c = 0; c < 3; c++){
    // ---- stage chunk c: rows [16c, 16c+16) of each trajectory ----
    __syncwarp();                    // previous chunk fully consumed (lockstep loop)
    for (int tt = 0; tt < tmax; tt++){
      const float* src = coords + (size_t)(base+tt)*(S*MD) + c*(CH*MD);
      float* dst = shC + tt*CST;
      #pragma unroll
      for (int it = 0; it < 5; it++)
        dst[it*32 + t] = src[it*32 + t];
    }
    __syncwarp();

    int rstart = 0;
    if (c == 0){
      // load row 0 into cur; row 0 always valid (n>=4)
      #pragma unroll
      for (int j=0;j<MD;j++){
        float v = shC[t*CST + j];
        cur[j] = v; sc += v; scq = fmaf(v,v,scq);
      }
      rstart = 1;
    }

    #pragma unroll 4
    for (int r = rstart; r < CH; r++){
      int gi = c*CH + r;            // global row 1..47
      int k  = gi - 1;              // delta index 0..46
      float nxt[MD];
      #pragma unroll
      for (int j=0;j<MD;j++) nxt[j] = shC[t*CST + r*MD + j];

      bool inrow = (gi < n);
      if (inrow){
        #pragma unroll
        for (int j=0;j<MD;j++){ sc += nxt[j]; scq = fmaf(nxt[j],nxt[j],scq); }
      }

      bool kv = (k < m);            // delta k valid
      float d[MD]; float dsq=0.f;
      #pragma unroll
      for (int j=0;j<MD;j++){ d[j] = nxt[j]-cur[j]; dsq = fmaf(d[j],d[j],dsq); }
      float dmag = (dsq>0.f) ? fsqrt_fast(fmaxf(dsq,1e-30f)) : 0.f;
      float inv  = __fdividef(1.f, fmaxf(dmag,1e-8f));

      if (kv){
        s_dm   += dmag;
        s_dmsq += dsq;
        if (k < half+1) s_f += dmag;
        if (k >= half)  s_s += dmag;
        mx_dm = fmaxf(mx_dm, dmag);
        #pragma unroll
        for (int j=0;j<MD;j++){ su[j] = fmaf(d[j],inv,su[j]); dv[j] += d[j]; }
        s_usq = fmaf(dsq, inv*inv, s_usq);
      }

      if (k >= 1){                  // cos index q = k-1 (uniform branch)
        float dot=0.f;
        #pragma unroll
        for (int j=0;j<MD;j++) dot = fmaf(pd[j], d[j], dot);
        float cs = dot * pinv * inv;
        float cv = 1.f - cs;
        if (kv){                    // cmask(q) == (k < m), per-lane
          s_curv   += cv;
          s_curvsq  = fmaf(cv,cv,s_curvsq);
          mx_curv   = fmaxf(mx_curv, cv);
          nmn_curv  = fmaxf(nmn_curv, -cv);
          s_cos    += cs;
          nmn_cos   = fmaxf(nmn_cos, -cs);
          if (cs < 0.f) s_neg += 1.f;
        }
        if (k <= 9)                 // padded curvs 0..8 (uniform branch)
          shFeat[t*FST + 51 + (k-1)] = kv ? cv : 0.f;
      }
      if (k < 3){                   // padded deltas 0..2 (always valid: m>=3)
        #pragma unroll
        for (int j=0;j<MD;j++) shFeat[t*FST + 21 + k*MD + j] = d[j];
      }

      #pragma unroll
      for (int j=0;j<MD;j++){ pd[j]=d[j]; cur[j]=nxt[j]; }
      pinv = inv;
    }
  }

  // ---- scalar features: fully parallel, each lane its own trajectory ----
  float mf  = (float)m;
  float ncf = (float)(n-2);
  float cnt = (float)(n*MD);
  float rncf = __fdividef(1.f, ncf);

  float mean_coord = __fdividef(sc, cnt);
  float coord_var  = __fdividef(scq - cnt*mean_coord*mean_coord, cnt-1.f);
  float std_coord  = fsqrt_fast(fmaxf(coord_var,1e-30f));

  float mean_dm = __fdividef(s_dm, mf);
  float dm_var  = __fdividef(s_dmsq - mf*mean_dm*mean_dm, fmaxf(mf-1.f,1.f));
  float std_dm  = fsqrt_fast(fmaxf(dm_var,1e-30f));        // mf>=3 always

  float mean_curv = s_curv * rncf;
  float curv_var  = __fdividef(s_curvsq - ncf*mean_curv*mean_curv, fmaxf(ncf-1.f,1.f));
  float std_curv  = (ncf>1.f) ? fsqrt_fast(fmaxf(curv_var,1e-30f)) : 0.f;

  float tsq=0.f, ssq=0.f;
  #pragma unroll
  for (int j=0;j<MD;j++){ tsq = fmaf(dv[j],dv[j],tsq); ssq = fmaf(su[j],su[j],ssq); }
  float total_disp = (tsq>0.f) ? fsqrt_fast(fmaxf(tsq,1e-30f)) : 0.f;

  float npairs      = mf*(mf-1.f)*0.5f;
  float parallelism = 0.5f*(ssq - s_usq)*__fdividef(1.f, fmaxf(npairs,1.f));

  float rpl = __fdividef(1.f, s_dm+1e-9f);
  float disp_ratio  = total_disp * rpl;
  float loop_score  = 1.f - total_disp * rpl;
  float fh  = __fdividef(s_f, (float)(half+1));
  float sh2 = __fdividef(s_s, (float)(m-half));
  float rfh = __fdividef(1.f, fh+1e-9f);
  float convergence = (fh-sh2)*rfh;
  float cascade     = (sh2-fh)*rfh;
  float mean_cos    = s_cos * rncf;
  float dir_changes = s_neg * __fdividef(1.f, fmaxf(ncf,1.f));
  float jump        = (mean_dm>1e-9f) ? __fdividef(mx_dm, mean_dm) : 1.f;

  float* fr = shFeat + t*FST;
  fr[0]=total_disp;  fr[1]=s_dm;        fr[2]=disp_ratio;   fr[3]=(float)n*0.1f;
  fr[4]=mean_curv;   fr[5]=mx_curv;     fr[6]=std_curv;     fr[7]=mx_curv-(-nmn_curv);
  fr[8]=mean_cos;    fr[9]=-nmn_cos;    fr[10]=dir_changes; fr[11]=disp_ratio;
  fr[12]=loop_score; fr[13]=convergence;fr[14]=parallelism; fr[15]=jump;
  fr[16]=cascade;    fr[17]=mean_dm;    fr[18]=std_dm;      fr[19]=mean_coord;
  fr[20]=std_coord;
  __syncwarp();

  // ---- flush features to gmem (coalesced) ----
  for (int tt = 0; tt < tmax; tt++){
    float* dst = g_feat + (size_t)(base+tt)*NF;
    const float* src = shFeat + tt*FST;
    dst[t] = src[t];
    if (t < NF-32) dst[t+32] = src[t+32];
  }
}

// ================= Kernel B: GEMV (60x48) + LayerNorm + GELU =================
#define WARPS 4
#define T     4
__global__ __launch_bounds__(WARPS*32)
void gemvB(const float* __restrict__ W, const float* __restrict__ bias,
           const float* __restrict__ ln_w, const float* __restrict__ ln_b,
           float* __restrict__ out, int B)
{
  __shared__ float shWt[H*WST];
  __shared__ float shB[H], shLw[H], shLb[H];
  __shared__ __align__(16) float shF[WARPS][T*NF];

  int tid = threadIdx.x;
  for (int idx = tid; idx < NF*H; idx += WARPS*32){
    int k = idx / H, h = idx - k*H;
    shWt[h*WST + k] = W[idx];
  }
  if (tid < H){ shB[tid]=bias[tid]; shLw[tid]=ln_w[tid]; shLb[tid]=ln_b[tid]; }
  __syncthreads();

  int w = tid >> 5, l = tid & 31;
  int b0 = (blockIdx.x*WARPS + w) * T;
  if (b0 >= B) return;
  int rem = B - b0;

  // stage T=4 consecutive trajectories' features (contiguous 240 floats)
  if (rem >= T){
    const float4* src4 = (const float4*)(g_feat + (size_t)b0*NF);
    float4* dst4 = (float4*)shF[w];
    if (l < 30){ dst4[l] = src4[l]; dst4[l+30] = src4[l+30]; }
  } else {
    const float* src = g_feat + (size_t)b0*NF;
    for (int e = l; e < rem*NF; e += 32) shF[w][e] = src[e];
  }
  __syncwarp();

  const float4* f4b = (const float4*)shF[w];
  const float4* wt0 = (const float4*)&shWt[l*WST];
  const float4* wt1 = (const float4*)&shWt[(l+32)*WST];
  float h0a[T], h1a[T];
  #pragma unroll
  for (int t=0;t<T;t++){ h0a[t]=shB[l]; h1a[t]=(l<16)?shB[l+32]:0.f; }

  #pragma unroll
  for (int k4=0; k4<NF/4; k4++){
    float4 w0 = wt0[k4];
    float4 w1 = make_float4(0.f,0.f,0.f,0.f);
    if (l<16) w1 = wt1[k4];
    #pragma unroll
    for (int t=0;t<T;t++){
      float4 fv = f4b[t*(NF/4)+k4];
      h0a[t] = fmaf(fv.x,w0.x,fmaf(fv.y,w0.y,fmaf(fv.z,w0.z,fmaf(fv.w,w0.w,h0a[t]))));
      h1a[t] = fmaf(fv.x,w1.x,fmaf(fv.y,w1.y,fmaf(fv.z,w1.z,fmaf(fv.w,w1.w,h1a[t]))));
    }
  }

  #pragma unroll
  for (int t=0;t<T;t++){
    int b = b0 + t;
    if (b >= B) break;
    float ssum2 = h0a[t] + ((l<16) ? h1a[t] : 0.f);
    float mu    = wsum(ssum2)*(1.f/48.f);
    float d0 = h0a[t] - mu, d1 = h1a[t] - mu;
    float vsum = d0*d0 + ((l<16) ? d1*d1 : 0.f);
    float var  = wsum(vsum)*(1.f/48.f);
    float inv  = rsqrtf(var+1e-5f);

    float g0 = d0*inv*shLw[l]+shLb[l];
    out[(size_t)b*H + l] = 0.5f*g0*(1.f+erff(g0*0.70710678118654752f));
    if (l<16){
      float g1 = d1*inv*shLw[l+32]+shLb[l+32];
      out[(size_t)b*H + l+32] = 0.5f*g1*(1.f+erff(g1*0.70710678118654752f));
    }
  }
}

extern "C" void kernel_launch(void* const* d_in, const int* in_sizes, int n_in,
                              void* d_out, int out_size) {
  const float* coords = (const float*)d_in[0];
  const int*   lengths= (const int*)  d_in[1];
  const float* W      = (const float*)d_in[2];
  const float* bias   = (const float*)d_in[3];
  const float* ln_w   = (const float*)d_in[4];
  const float* ln_b   = (const float*)d_in[5];
  float* out = (float*)d_out;
  int B = in_sizes[0] / (S*MD);
  int gridA = (B + 31) / 32;
  featA<<<gridA, 32>>>(coords, lengths, B);
  int gridB = (B + WARPS*T - 1) / (WARPS*T);
  gemvB<<<gridB, WARPS*32>>>(W, bias, ln_w, ln_b, out, B);
}